// round 3
// baseline (speedup 1.0000x reference)
#include <cuda_runtime.h>
#include <cstdint>
#include <cstddef>

#define NG   50
#define NF   64
#define DIM  128

typedef unsigned long long ull;

// ---------------- f32x2 helpers (Blackwell packed fp32) ----------------
__device__ __forceinline__ ull pk2(float lo, float hi){
    ull r; asm("mov.b64 %0, {%1, %2};" : "=l"(r) : "f"(lo), "f"(hi)); return r;
}
__device__ __forceinline__ float2 up2(ull v){
    float2 f; asm("mov.b64 {%0, %1}, %2;" : "=f"(f.x), "=f"(f.y) : "l"(v)); return f;
}
__device__ __forceinline__ ull ffma2(ull a, ull b, ull c){
    ull d; asm("fma.rn.f32x2 %0, %1, %2, %3;" : "=l"(d) : "l"(a), "l"(b), "l"(c)); return d;
}
__device__ __forceinline__ ull fmul2(ull a, ull b){
    ull d; asm("mul.rn.f32x2 %0, %1, %2;" : "=l"(d) : "l"(a), "l"(b)); return d;
}
__device__ __forceinline__ ull fadd2(ull a, ull b){
    ull d; asm("add.rn.f32x2 %0, %1, %2;" : "=l"(d) : "l"(a), "l"(b)); return d;
}

// shifted softplus: softplus(x) - log(2), numerically stable
__device__ __forceinline__ float sspf(float x){
    float e = __expf(-fabsf(x));
    return fmaxf(x, 0.0f) + __logf(1.0f + e) - 0.69314718055994531f;
}

// ---------------- scratch (static device arrays; no allocation) --------
#define MAXN 100000
__device__ __align__(16) float g_h  [MAXN * NF];
__device__ __align__(16) float g_agg[MAXN * NF];
__device__ __align__(16) float g_h2 [(size_t)MAXN * DIM];
__device__ __align__(16) float g_h3 [(size_t)MAXN * DIM];

// =======================================================================
// K1: h[n,64] = x[n,128] @ conv_lin1_w[128,64]  (no bias); also zero agg.
// =======================================================================
__global__ void __launch_bounds__(128) k_node_in(
    const float* __restrict__ x, const float* __restrict__ w, int N)
{
    __shared__ __align__(16) float sw[DIM * NF];           // 32 KB
    for (int i = threadIdx.x; i < DIM * NF; i += blockDim.x) sw[i] = w[i];
    __syncthreads();

    int n = blockIdx.x * blockDim.x + threadIdx.x;
    if (n >= N) return;

    ull acc[NF/2];
    #pragma unroll
    for (int i = 0; i < NF/2; i++) acc[i] = 0ULL;

    const float4* x4 = (const float4*)(x + (size_t)n * DIM);
    #pragma unroll 4
    for (int kk = 0; kk < DIM/4; kk++){
        float4 xv = __ldg(&x4[kk]);
        float xs[4] = {xv.x, xv.y, xv.z, xv.w};
        #pragma unroll
        for (int q = 0; q < 4; q++){
            int k = kk*4 + q;
            ull bx = pk2(xs[q], xs[q]);
            const ulonglong2* wr = (const ulonglong2*)(sw + k * NF);
            #pragma unroll
            for (int i = 0; i < NF/4; i++){
                ulonglong2 wv = wr[i];
                acc[2*i]   = ffma2(bx, wv.x, acc[2*i]);
                acc[2*i+1] = ffma2(bx, wv.y, acc[2*i+1]);
            }
        }
    }

    float4* hd = (float4*)(g_h   + (size_t)n * NF);
    float4* ad = (float4*)(g_agg + (size_t)n * NF);
    #pragma unroll
    for (int i = 0; i < NF/4; i++){
        float2 a = up2(acc[2*i]), b = up2(acc[2*i+1]);
        hd[i] = make_float4(a.x, a.y, b.x, b.y);
        ad[i] = make_float4(0.f, 0.f, 0.f, 0.f);
    }
}

// =======================================================================
// K2: fused per-edge: dist -> gaussians -> MLP1(+ssp) -> MLP2 (two output
// halves to cap register pressure) -> *C -> msg = h[src]*W
// -> red.add.v4 into agg[dst]
// edge_index is int32 (JAX downcasts int64 without x64 mode).
// =======================================================================
__global__ void __launch_bounds__(128) k_edge(
    const int* __restrict__ ei, const float* __restrict__ pos,
    const float* __restrict__ w1, const float* __restrict__ b1,
    const float* __restrict__ w2, const float* __restrict__ b2,
    int E)
{
    __shared__ __align__(16) float s_w1[NG * NF];   // 12.5 KB
    __shared__ __align__(16) float s_w2[NF * NF];   // 16 KB
    __shared__ __align__(16) float s_b1[NF];
    __shared__ __align__(16) float s_b2[NF];

    for (int i = threadIdx.x; i < NG * NF; i += blockDim.x) s_w1[i] = w1[i];
    for (int i = threadIdx.x; i < NF * NF; i += blockDim.x) s_w2[i] = w2[i];
    if (threadIdx.x < NF){
        s_b1[threadIdx.x] = b1[threadIdx.x];
        s_b2[threadIdx.x] = b2[threadIdx.x];
    }
    __syncthreads();

    int e = blockIdx.x * blockDim.x + threadIdx.x;
    if (e >= E) return;

    int s = __ldg(&ei[e]);
    int d = __ldg(&ei[E + e]);

    float dx = __ldg(&pos[d*3+0]) - __ldg(&pos[s*3+0]);
    float dy = __ldg(&pos[d*3+1]) - __ldg(&pos[s*3+1]);
    float dz = __ldg(&pos[d*3+2]) - __ldg(&pos[s*3+2]);
    float dist = sqrtf(dx*dx + dy*dy + dz*dz);

    const float delta = 10.0f / 49.0f;
    const float coeff = -0.5f / (delta * delta);

    // ---- MLP1: [50] @ [50,64] + b1, then shifted-softplus ----
    ull acc[NF/2];
    {
        const ull* b1p = (const ull*)s_b1;
        #pragma unroll
        for (int i = 0; i < NF/2; i++) acc[i] = b1p[i];
    }

    #pragma unroll 1
    for (int g = 0; g < NG; g++){
        float t  = dist - (float)g * delta;
        float eg = __expf(coeff * t * t);
        ull be = pk2(eg, eg);
        const ulonglong2* wr = (const ulonglong2*)(s_w1 + g * NF);
        #pragma unroll
        for (int i = 0; i < NF/4; i++){
            ulonglong2 wv = wr[i];
            acc[2*i]   = ffma2(be, wv.x, acc[2*i]);
            acc[2*i+1] = ffma2(be, wv.y, acc[2*i+1]);
        }
    }

    #pragma unroll
    for (int i = 0; i < NF/2; i++){
        float2 v = up2(acc[i]);
        acc[i] = pk2(sspf(v.x), sspf(v.y));
    }

    // ---- cosine cutoff ----
    float C = 0.5f * (__cosf(dist * 0.31415926535897932f) + 1.0f);
    ull bc = pk2(C, C);

    const float4* hs = (const float4*)(g_h + (size_t)s * NF);
    float* ad = g_agg + (size_t)d * NF;

    // ---- MLP2 in two output halves of 32 (caps live registers) ----
    #pragma unroll 1
    for (int half = 0; half < 2; half++){
        ull acc2[16];
        {
            const ull* b2p = (const ull*)(s_b2 + half * 32);
            #pragma unroll
            for (int i = 0; i < 16; i++) acc2[i] = b2p[i];
        }

        #pragma unroll 4
        for (int jp = 0; jp < NF/2; jp++){
            float2 hv = up2(acc[jp]);
            ull ba = pk2(hv.x, hv.x);
            ull bb = pk2(hv.y, hv.y);
            const ulonglong2* r0 = (const ulonglong2*)(s_w2 + (2*jp)   * NF + half * 32);
            const ulonglong2* r1 = (const ulonglong2*)(s_w2 + (2*jp+1) * NF + half * 32);
            #pragma unroll
            for (int i = 0; i < 8; i++){
                ulonglong2 w0 = r0[i];
                acc2[2*i]   = ffma2(ba, w0.x, acc2[2*i]);
                acc2[2*i+1] = ffma2(ba, w0.y, acc2[2*i+1]);
            }
            #pragma unroll
            for (int i = 0; i < 8; i++){
                ulonglong2 wv = r1[i];
                acc2[2*i]   = ffma2(bb, wv.x, acc2[2*i]);
                acc2[2*i+1] = ffma2(bb, wv.y, acc2[2*i+1]);
            }
        }

        // gather h[src], apply cutoff, scatter-add to agg[dst]
        #pragma unroll
        for (int i = 0; i < 8; i++){
            float4 hv = __ldg(&hs[half*8 + i]);
            float2 wA = up2(fmul2(acc2[2*i],   bc));
            float2 wB = up2(fmul2(acc2[2*i+1], bc));
            float m0 = hv.x * wA.x;
            float m1 = hv.y * wA.y;
            float m2 = hv.z * wB.x;
            float m3 = hv.w * wB.y;
            asm volatile("red.global.add.v4.f32 [%0], {%1, %2, %3, %4};"
                         :: "l"(ad + half*32 + 4*i),
                            "f"(m0), "f"(m1), "f"(m2), "f"(m3)
                         : "memory");
        }
    }
}

// =======================================================================
// K3a: h2[n,128] = ssp(agg[n,64] @ conv_lin2_w[64,128] + b)
// =======================================================================
__global__ void __launch_bounds__(128) k_tail1(
    const float* __restrict__ w, const float* __restrict__ b, int N)
{
    __shared__ __align__(16) float sw[NF * DIM];    // 32 KB
    __shared__ __align__(16) float sb[DIM];
    for (int i = threadIdx.x; i < NF * DIM; i += blockDim.x) sw[i] = w[i];
    sb[threadIdx.x] = b[threadIdx.x];
    __syncthreads();

    int n = blockIdx.x * blockDim.x + threadIdx.x;
    if (n >= N) return;

    ull acc[DIM/2];
    {
        const ull* bp = (const ull*)sb;
        #pragma unroll
        for (int i = 0; i < DIM/2; i++) acc[i] = bp[i];
    }

    const float4* a4 = (const float4*)(g_agg + (size_t)n * NF);
    #pragma unroll 4
    for (int kk = 0; kk < NF/4; kk++){
        float4 av = __ldg(&a4[kk]);
        float as[4] = {av.x, av.y, av.z, av.w};
        #pragma unroll
        for (int q = 0; q < 4; q++){
            int k = kk*4 + q;
            ull bx = pk2(as[q], as[q]);
            const ulonglong2* wr = (const ulonglong2*)(sw + k * DIM);
            #pragma unroll
            for (int i = 0; i < DIM/4; i++){
                ulonglong2 wv = wr[i];
                acc[2*i]   = ffma2(bx, wv.x, acc[2*i]);
                acc[2*i+1] = ffma2(bx, wv.y, acc[2*i+1]);
            }
        }
    }

    float4* od = (float4*)(g_h2 + (size_t)n * DIM);
    #pragma unroll
    for (int i = 0; i < DIM/4; i++){
        float2 a = up2(acc[2*i]), c = up2(acc[2*i+1]);
        od[i] = make_float4(sspf(a.x), sspf(a.y), sspf(c.x), sspf(c.y));
    }
}

// =======================================================================
// K3b/K3c: 128x128 GEMV per node, weight staged through 32 KB smem in
// two k-halves (no dynamic smem, no cudaFuncSetAttribute needed).
//   MODE 0: g_h3 = g_h2 @ int_lin_w + b
//   MODE 1: out  = x + relu(g_h3 @ lin1_w + b)
// =======================================================================
template <int MODE>
__global__ void __launch_bounds__(128) k_tail2(
    const float* __restrict__ w, const float* __restrict__ b,
    const float* __restrict__ x, float* __restrict__ out, int N)
{
    __shared__ __align__(16) float sw[64 * DIM];    // 32 KB
    __shared__ __align__(16) float sb[DIM];
    sb[threadIdx.x] = b[threadIdx.x];

    int n = blockIdx.x * blockDim.x + threadIdx.x;
    bool valid = (n < N);

    ull acc[DIM/2];
    #pragma unroll
    for (int i = 0; i < DIM/2; i++) acc[i] = 0ULL;

    const float* in = (MODE == 0) ? g_h2 : g_h3;
    const float4* a4 = (const float4*)(in + (size_t)n * DIM);

    #pragma unroll 1
    for (int st = 0; st < 2; st++){
        __syncthreads();   // protect sw from previous stage's readers
        for (int i = threadIdx.x; i < 64 * DIM; i += blockDim.x)
            sw[i] = w[st * 64 * DIM + i];
        __syncthreads();

        if (valid){
            #pragma unroll 4
            for (int kk = 0; kk < 16; kk++){
                float4 av = __ldg(&a4[st*16 + kk]);
                float as[4] = {av.x, av.y, av.z, av.w};
                #pragma unroll
                for (int q = 0; q < 4; q++){
                    int k = kk*4 + q;
                    ull bx = pk2(as[q], as[q]);
                    const ulonglong2* wr = (const ulonglong2*)(sw + k * DIM);
                    #pragma unroll
                    for (int i = 0; i < DIM/4; i++){
                        ulonglong2 wv = wr[i];
                        acc[2*i]   = ffma2(bx, wv.x, acc[2*i]);
                        acc[2*i+1] = ffma2(bx, wv.y, acc[2*i+1]);
                    }
                }
            }
        }
    }

    if (!valid) return;

    // add bias
    {
        const ull* bp = (const ull*)sb;
        #pragma unroll
        for (int i = 0; i < DIM/2; i++) acc[i] = fadd2(acc[i], bp[i]);
    }

    if (MODE == 0){
        float4* od = (float4*)(g_h3 + (size_t)n * DIM);
        #pragma unroll
        for (int i = 0; i < DIM/4; i++){
            float2 a = up2(acc[2*i]), c = up2(acc[2*i+1]);
            od[i] = make_float4(a.x, a.y, c.x, c.y);
        }
    } else {
        const float4* xv4 = (const float4*)(x + (size_t)n * DIM);
        float4* od = (float4*)(out + (size_t)n * DIM);
        #pragma unroll
        for (int i = 0; i < DIM/4; i++){
            float2 a = up2(acc[2*i]), c = up2(acc[2*i+1]);
            float4 xv = __ldg(&xv4[i]);
            od[i] = make_float4(xv.x + fmaxf(a.x, 0.f),
                                xv.y + fmaxf(a.y, 0.f),
                                xv.z + fmaxf(c.x, 0.f),
                                xv.w + fmaxf(c.y, 0.f));
        }
    }
}

// =======================================================================
extern "C" void kernel_launch(void* const* d_in, const int* in_sizes, int n_in,
                              void* d_out, int out_size)
{
    const float* x    = (const float*)d_in[0];
    const float* pos  = (const float*)d_in[1];
    const int*   ei   = (const int*)d_in[2];
    const float* w1   = (const float*)d_in[3];
    const float* b1   = (const float*)d_in[4];
    const float* w2   = (const float*)d_in[5];
    const float* b2   = (const float*)d_in[6];
    const float* cl1  = (const float*)d_in[7];
    const float* cl2  = (const float*)d_in[8];
    const float* cl2b = (const float*)d_in[9];
    const float* ilw  = (const float*)d_in[10];
    const float* ilb  = (const float*)d_in[11];
    const float* l1w  = (const float*)d_in[12];
    const float* l1b  = (const float*)d_in[13];
    float* out = (float*)d_out;

    int N = in_sizes[0] / DIM;
    int E = in_sizes[2] / 2;

    int nb = (N + 127) / 128;
    int eb = (E + 127) / 128;

    k_node_in<<<nb, 128>>>(x, cl1, N);
    k_edge  <<<eb, 128>>>(ei, pos, w1, b1, w2, b2, E);
    k_tail1 <<<nb, 128>>>(cl2, cl2b, N);
    k_tail2<0><<<nb, 128>>>(ilw, ilb, nullptr, nullptr, N);
    k_tail2<1><<<nb, 128>>>(l1w, l1b, x, out, N);
}

// round 5
// speedup vs baseline: 1.8999x; 1.8999x over previous
#include <cuda_runtime.h>
#include <cstdint>
#include <cstddef>

#define NG   50
#define NF   64
#define DIM  128

typedef unsigned long long ull;

// ---------------- f32x2 helpers (Blackwell packed fp32) ----------------
__device__ __forceinline__ ull pk2(float lo, float hi){
    ull r; asm("mov.b64 %0, {%1, %2};" : "=l"(r) : "f"(lo), "f"(hi)); return r;
}
__device__ __forceinline__ float2 up2(ull v){
    float2 f; asm("mov.b64 {%0, %1}, %2;" : "=f"(f.x), "=f"(f.y) : "l"(v)); return f;
}
__device__ __forceinline__ ull ffma2(ull a, ull b, ull c){
    ull d; asm("fma.rn.f32x2 %0, %1, %2, %3;" : "=l"(d) : "l"(a), "l"(b), "l"(c)); return d;
}
__device__ __forceinline__ ull fadd2(ull a, ull b){
    ull d; asm("add.rn.f32x2 %0, %1, %2;" : "=l"(d) : "l"(a), "l"(b)); return d;
}

// shifted softplus
__device__ __forceinline__ float sspf(float x){
    float e = __expf(-fabsf(x));
    return fmaxf(x, 0.0f) + __logf(1.0f + e) - 0.69314718055994531f;
}

// ---------------- scratch ----------------
#define MAXN 100000
#define TBL  16384                 // bins over dist in [0,16]; width 1/1024
#define TBL_ROWS (TBL + 2)
__device__ __align__(16) float g_h  [MAXN * NF];
__device__ __align__(16) float g_agg[MAXN * NF];
__device__ __align__(16) float g_h2 [(size_t)MAXN * DIM];
__device__ __align__(16) float g_h3 [(size_t)MAXN * DIM];
__device__ __align__(16) float g_T  [(size_t)TBL_ROWS * NF];   // W(dist)*C(dist)

// =======================================================================
// Table kernel: for each bin, full filter MLP * cosine cutoff.
// T[b][:] = (ssp(gauss(d_b) @ w1 + b1) @ w2 + b2) * C(d_b),  d_b = b/1024
// =======================================================================
__global__ void __launch_bounds__(128) k_table(
    const float* __restrict__ w1, const float* __restrict__ b1,
    const float* __restrict__ w2, const float* __restrict__ b2)
{
    __shared__ __align__(16) float s_w1[NG * NF];
    __shared__ __align__(16) float s_w2[NF * NF];
    __shared__ __align__(16) float s_b1[NF];
    __shared__ __align__(16) float s_b2[NF];

    for (int i = threadIdx.x; i < NG * NF; i += blockDim.x) s_w1[i] = w1[i];
    for (int i = threadIdx.x; i < NF * NF; i += blockDim.x) s_w2[i] = w2[i];
    if (threadIdx.x < NF){
        s_b1[threadIdx.x] = b1[threadIdx.x];
        s_b2[threadIdx.x] = b2[threadIdx.x];
    }
    __syncthreads();

    int bin = blockIdx.x * blockDim.x + threadIdx.x;
    if (bin > TBL) return;
    float dist = (float)bin * (1.0f / 1024.0f);

    const float delta = 10.0f / 49.0f;
    const float coeff = -0.5f / (delta * delta);

    // MLP1 + ssp
    float acc[NF];
    #pragma unroll
    for (int i = 0; i < NF; i++) acc[i] = s_b1[i];
    for (int g = 0; g < NG; g++){
        float t  = dist - (float)g * delta;
        float eg = __expf(coeff * t * t);
        #pragma unroll
        for (int i = 0; i < NF; i++) acc[i] = fmaf(eg, s_w1[g*NF + i], acc[i]);
    }
    #pragma unroll
    for (int i = 0; i < NF; i++) acc[i] = sspf(acc[i]);

    // MLP2
    float acc2[NF];
    #pragma unroll
    for (int i = 0; i < NF; i++) acc2[i] = s_b2[i];
    for (int j = 0; j < NF; j++){
        float a = acc[j];
        #pragma unroll
        for (int i = 0; i < NF; i++) acc2[i] = fmaf(a, s_w2[j*NF + i], acc2[i]);
    }

    float C = 0.5f * (__cosf(dist * 0.31415926535897932f) + 1.0f);
    float* dst = g_T + (size_t)bin * NF;
    #pragma unroll
    for (int i = 0; i < NF; i++) dst[i] = acc2[i] * C;
}

// =======================================================================
// Edge kernel: dist -> table lerp -> msg = h[src]*W -> red.v4 agg[dst]
// =======================================================================
__global__ void __launch_bounds__(256) k_edge(
    const int* __restrict__ ei, const float* __restrict__ pos, int E)
{
    int e = blockIdx.x * blockDim.x + threadIdx.x;
    if (e >= E) return;

    int s = __ldg(&ei[e]);
    int d = __ldg(&ei[E + e]);

    float dx = __ldg(&pos[d*3+0]) - __ldg(&pos[s*3+0]);
    float dy = __ldg(&pos[d*3+1]) - __ldg(&pos[s*3+1]);
    float dz = __ldg(&pos[d*3+2]) - __ldg(&pos[s*3+2]);
    float dist = sqrtf(dx*dx + dy*dy + dz*dz);

    float t = fminf(dist * 1024.0f, 16383.99f);
    int   i = (int)t;
    float f = t - (float)i;

    const float4* r0 = (const float4*)(g_T + (size_t)i * NF);
    const float4* r1 = r0 + (NF/4);
    const float4* hs = (const float4*)(g_h + (size_t)s * NF);
    float* ad = g_agg + (size_t)d * NF;

    #pragma unroll
    for (int j = 0; j < NF/4; j++){
        float4 a  = __ldg(&r0[j]);
        float4 b  = __ldg(&r1[j]);
        float4 hv = __ldg(&hs[j]);
        float w0 = fmaf(f, b.x - a.x, a.x);
        float w1 = fmaf(f, b.y - a.y, a.y);
        float w2 = fmaf(f, b.z - a.z, a.z);
        float w3 = fmaf(f, b.w - a.w, a.w);
        float m0 = hv.x * w0;
        float m1 = hv.y * w1;
        float m2 = hv.z * w2;
        float m3 = hv.w * w3;
        asm volatile("red.global.add.v4.f32 [%0], {%1, %2, %3, %4};"
                     :: "l"(ad + 4*j), "f"(m0), "f"(m1), "f"(m2), "f"(m3)
                     : "memory");
    }
}

// =======================================================================
// Register-tiled GEMM: OUT[n, :NO] = act(IN[n, :K] @ W[K,NO] + bias)
// Block = 256 threads (tx 0..15 = output chunk, ty 0..15 = node slice),
// covers 128 nodes. Each thread: 8 nodes x NC outputs, f32x2 accumulators.
//   ACT: 0=none, 1=ssp, 2=relu ; RESID adds resid[] after relu
//   ZERO: also zero g_agg rows (node_in)
//   INSEL: 0=ext, 1=g_agg, 2=g_h2, 3=g_h3 ; OUTSEL: 0=ext, 1=g_h, 2=g_h2, 3=g_h3
// =======================================================================
template<int K, int NO, int ACT, bool RESID, bool ZERO, int INSEL, int OUTSEL>
__global__ void __launch_bounds__(256, 2) k_gemm(
    const float* __restrict__ ein, const float* __restrict__ w,
    const float* __restrict__ bias, const float* __restrict__ resid,
    float* __restrict__ eout, int N)
{
    constexpr int NC = NO / 16;          // outputs per thread (4 or 8)
    constexpr int KS = (K > 64) ? 64 : K;
    constexpr int NSTAGE = K / KS;

    __shared__ __align__(16) float sw[KS * NO];   // <= 32 KB
    __shared__ __align__(16) float sb[NO];

    int tid = threadIdx.x;
    int tx = tid & 15, ty = tid >> 4;
    if (tid < NO) sb[tid] = bias ? bias[tid] : 0.0f;

    const float* inp = (INSEL == 0) ? ein
                     : (INSEL == 1) ? (const float*)g_agg
                     : (INSEL == 2) ? (const float*)g_h2
                     :                (const float*)g_h3;
    float* outp = (OUTSEL == 0) ? eout
                : (OUTSEL == 1) ? (float*)g_h
                : (OUTSEL == 2) ? (float*)g_h2
                :                 (float*)g_h3;

    int nb = blockIdx.x * 128;
    int  nn[8];
    bool vld[8];
    #pragma unroll
    for (int r = 0; r < 8; r++){
        int n = nb + ty + 16*r;
        vld[r] = (n < N);
        nn[r]  = vld[r] ? n : 0;
    }

    ull acc[8][NC/2];
    #pragma unroll
    for (int r = 0; r < 8; r++)
        #pragma unroll
        for (int j = 0; j < NC/2; j++) acc[r][j] = 0ULL;

    #pragma unroll 1
    for (int st = 0; st < NSTAGE; st++){
        __syncthreads();
        for (int i = tid; i < KS * NO; i += 256) sw[i] = w[st*KS*NO + i];
        __syncthreads();

        #pragma unroll 1
        for (int kc = 0; kc < KS/4; kc++){
            float4 xv[8];
            #pragma unroll
            for (int r = 0; r < 8; r++)
                xv[r] = __ldg((const float4*)(inp + (size_t)nn[r]*K) + st*(KS/4) + kc);

            #pragma unroll
            for (int q = 0; q < 4; q++){
                int k = kc*4 + q;
                const ulonglong2* wr = (const ulonglong2*)(sw + k*NO + tx*NC);
                ulonglong2 wu[NC/4];
                #pragma unroll
                for (int j = 0; j < NC/4; j++) wu[j] = wr[j];

                #pragma unroll
                for (int r = 0; r < 8; r++){
                    float xq = (q == 0) ? xv[r].x : (q == 1) ? xv[r].y
                             : (q == 2) ? xv[r].z : xv[r].w;
                    ull bx = pk2(xq, xq);
                    #pragma unroll
                    for (int j = 0; j < NC/4; j++){
                        acc[r][2*j]   = ffma2(bx, wu[j].x, acc[r][2*j]);
                        acc[r][2*j+1] = ffma2(bx, wu[j].y, acc[r][2*j+1]);
                    }
                }
            }
        }
    }

    // epilogue
    const ull* sb2 = (const ull*)(sb + tx*NC);
    #pragma unroll
    for (int r = 0; r < 8; r++){
        if (!vld[r]) continue;
        int n = nn[r];
        float o[NC];
        #pragma unroll
        for (int j = 0; j < NC/2; j++){
            float2 p = up2(fadd2(acc[r][j], sb2[j]));
            if (ACT == 1){ p.x = sspf(p.x); p.y = sspf(p.y); }
            if (ACT == 2){ p.x = fmaxf(p.x, 0.f); p.y = fmaxf(p.y, 0.f); }
            o[2*j]   = p.x;
            o[2*j+1] = p.y;
        }
        if (RESID){
            const float4* rv = (const float4*)(resid + (size_t)n*NO + tx*NC);
            #pragma unroll
            for (int j = 0; j < NC/4; j++){
                float4 v = __ldg(&rv[j]);
                o[4*j]   += v.x; o[4*j+1] += v.y;
                o[4*j+2] += v.z; o[4*j+3] += v.w;
            }
        }
        float4* od = (float4*)(outp + (size_t)n*NO + tx*NC);
        #pragma unroll
        for (int j = 0; j < NC/4; j++)
            od[j] = make_float4(o[4*j], o[4*j+1], o[4*j+2], o[4*j+3]);

        if (ZERO){   // node_in: zero agg[n][tx*4 .. +4]  (NO==64, NC==4)
            float4* az = (float4*)(g_agg + (size_t)n*NF + tx*4);
            *az = make_float4(0.f, 0.f, 0.f, 0.f);
        }
    }
}

// =======================================================================
extern "C" void kernel_launch(void* const* d_in, const int* in_sizes, int n_in,
                              void* d_out, int out_size)
{
    const float* x    = (const float*)d_in[0];
    const float* pos  = (const float*)d_in[1];
    const int*   ei   = (const int*)d_in[2];
    const float* w1   = (const float*)d_in[3];
    const float* b1   = (const float*)d_in[4];
    const float* w2   = (const float*)d_in[5];
    const float* b2   = (const float*)d_in[6];
    const float* cl1  = (const float*)d_in[7];
    const float* cl2  = (const float*)d_in[8];
    const float* cl2b = (const float*)d_in[9];
    const float* ilw  = (const float*)d_in[10];
    const float* ilb  = (const float*)d_in[11];
    const float* l1w  = (const float*)d_in[12];
    const float* l1b  = (const float*)d_in[13];
    float* out = (float*)d_out;

    int N = in_sizes[0] / DIM;
    int E = in_sizes[2] / 2;

    int nb = (N + 127) / 128;
    int eb = (E + 255) / 256;
    int tb = (TBL + 1 + 127) / 128;

    // filter table (independent of node path)
    k_table<<<tb, 128>>>(w1, b1, w2, b2);

    // h = x @ conv_lin1_w ; zero agg
    k_gemm<DIM, NF, 0, false, true, 0, 1><<<nb, 256>>>(x, cl1, nullptr, nullptr, nullptr, N);

    // edge scatter
    k_edge<<<eb, 256>>>(ei, pos, E);

    // h2 = ssp(agg @ conv_lin2_w + b)
    k_gemm<NF, DIM, 1, false, false, 1, 2><<<nb, 256>>>(nullptr, cl2, cl2b, nullptr, nullptr, N);

    // h3 = h2 @ int_lin_w + b
    k_gemm<DIM, DIM, 0, false, false, 2, 3><<<nb, 256>>>(nullptr, ilw, ilb, nullptr, nullptr, N);

    // out = x + relu(h3 @ lin1_w + b)
    k_gemm<DIM, DIM, 2, true, false, 3, 0><<<nb, 256>>>(nullptr, l1w, l1b, x, out, N);
}

// round 7
// speedup vs baseline: 2.9322x; 1.5434x over previous
#include <cuda_runtime.h>
#include <cstdint>
#include <cstddef>

#define NG   50
#define NF   64
#define DIM  128

typedef unsigned long long ull;

// ---------------- f32x2 helpers (Blackwell packed fp32) ----------------
__device__ __forceinline__ ull pk2(float lo, float hi){
    ull r; asm("mov.b64 %0, {%1, %2};" : "=l"(r) : "f"(lo), "f"(hi)); return r;
}
__device__ __forceinline__ float2 up2(ull v){
    float2 f; asm("mov.b64 {%0, %1}, %2;" : "=f"(f.x), "=f"(f.y) : "l"(v)); return f;
}
__device__ __forceinline__ ull ffma2(ull a, ull b, ull c){
    ull d; asm("fma.rn.f32x2 %0, %1, %2, %3;" : "=l"(d) : "l"(a), "l"(b), "l"(c)); return d;
}
__device__ __forceinline__ ull fadd2(ull a, ull b){
    ull d; asm("add.rn.f32x2 %0, %1, %2;" : "=l"(d) : "l"(a), "l"(b)); return d;
}

// shifted softplus
__device__ __forceinline__ float sspf(float x){
    float e = __expf(-fabsf(x));
    return fmaxf(x, 0.0f) + __logf(1.0f + e) - 0.69314718055994531f;
}

// ---------------- scratch ----------------
#define MAXN 100000
#define TBL  16384                 // bins over dist in [0,16]; width 1/1024
#define TBL_ROWS (TBL + 2)
__device__ __align__(16) float g_h  [MAXN * NF];
__device__ __align__(16) float g_agg[MAXN * NF];
__device__ __align__(16) float g_h2 [(size_t)MAXN * DIM];
__device__ __align__(16) float g_h3 [(size_t)MAXN * DIM];
__device__ __align__(16) float g_T  [(size_t)TBL_ROWS * NF];   // W(dist)*C(dist)

// =======================================================================
// Table kernel: T[b][:] = (ssp(gauss(d_b)@w1+b1)@w2+b2)*C(d_b), d_b=b/1024
// 4 threads per bin (16 outputs each), ssp intermediate staged in smem.
// Block = 128 threads = 32 bins.
// =======================================================================
__global__ void __launch_bounds__(128) k_table(
    const float* __restrict__ w1, const float* __restrict__ b1,
    const float* __restrict__ w2, const float* __restrict__ b2)
{
    __shared__ __align__(16) float s_w1[NG * NF];
    __shared__ __align__(16) float s_w2[NF * NF];
    __shared__ __align__(16) float s_b1[NF];
    __shared__ __align__(16) float s_b2[NF];
    __shared__ float s_mid[32][NF + 1];     // padded: conflict-free

    for (int i = threadIdx.x; i < NG * NF; i += blockDim.x) s_w1[i] = w1[i];
    for (int i = threadIdx.x; i < NF * NF; i += blockDim.x) s_w2[i] = w2[i];
    if (threadIdx.x < NF){
        s_b1[threadIdx.x] = b1[threadIdx.x];
        s_b2[threadIdx.x] = b2[threadIdx.x];
    }
    __syncthreads();

    int q  = threadIdx.x & 3;        // output quarter (16 outputs)
    int bl = threadIdx.x >> 2;       // local bin 0..31
    int bin = blockIdx.x * 32 + bl;
    float dist = (float)bin * (1.0f / 1024.0f);

    const float delta = 10.0f / 49.0f;
    const float coeff = -0.5f / (delta * delta);

    // phase A: MLP1 quarter + ssp -> smem
    float acc[16];
    #pragma unroll
    for (int i = 0; i < 16; i++) acc[i] = s_b1[q*16 + i];
    for (int g = 0; g < NG; g++){
        float t  = dist - (float)g * delta;
        float eg = __expf(coeff * t * t);
        #pragma unroll
        for (int i = 0; i < 16; i++) acc[i] = fmaf(eg, s_w1[g*NF + q*16 + i], acc[i]);
    }
    #pragma unroll
    for (int i = 0; i < 16; i++) s_mid[bl][q*16 + i] = sspf(acc[i]);
    __syncthreads();

    // phase B: MLP2 quarter
    float acc2[16];
    #pragma unroll
    for (int i = 0; i < 16; i++) acc2[i] = s_b2[q*16 + i];
    for (int j = 0; j < NF; j++){
        float a = s_mid[bl][j];
        #pragma unroll
        for (int i = 0; i < 16; i++) acc2[i] = fmaf(a, s_w2[j*NF + q*16 + i], acc2[i]);
    }

    if (bin <= TBL){
        float C = 0.5f * (__cosf(dist * 0.31415926535897932f) + 1.0f);
        float* dst = g_T + (size_t)bin * NF + q*16;
        #pragma unroll
        for (int i = 0; i < 16; i++) dst[i] = acc2[i] * C;
    }
}

// =======================================================================
// Edge kernel, coalesced: 16 lanes per edge, lane j owns float4 chunk j.
// All row accesses (table pair, h[src], agg RED) contiguous per edge.
// =======================================================================
__global__ void __launch_bounds__(256) k_edge(
    const int* __restrict__ ei, const float* __restrict__ pos, int E)
{
    int gid = blockIdx.x * 256 + threadIdx.x;
    int e = gid >> 4;
    int j = gid & 15;
    if (e >= E) return;

    int s = __ldg(&ei[e]);
    int d = __ldg(&ei[E + e]);

    float dx = __ldg(&pos[d*3+0]) - __ldg(&pos[s*3+0]);
    float dy = __ldg(&pos[d*3+1]) - __ldg(&pos[s*3+1]);
    float dz = __ldg(&pos[d*3+2]) - __ldg(&pos[s*3+2]);
    float dist = sqrtf(dx*dx + dy*dy + dz*dz);

    float t = fminf(dist * 1024.0f, 16383.99f);
    int   i = (int)t;
    float f = t - (float)i;

    const float4* tp = (const float4*)(g_T + (size_t)i * NF) + j;
    float4 a  = __ldg(tp);
    float4 b  = __ldg(tp + NF/4);
    float4 hv = __ldg((const float4*)(g_h + (size_t)s * NF) + j);

    float m0 = hv.x * fmaf(f, b.x - a.x, a.x);
    float m1 = hv.y * fmaf(f, b.y - a.y, a.y);
    float m2 = hv.z * fmaf(f, b.z - a.z, a.z);
    float m3 = hv.w * fmaf(f, b.w - a.w, a.w);

    asm volatile("red.global.add.v4.f32 [%0], {%1, %2, %3, %4};"
                 :: "l"(g_agg + (size_t)d * NF + 4*j),
                    "f"(m0), "f"(m1), "f"(m2), "f"(m3)
                 : "memory");
}

// =======================================================================
// Register-tiled GEMM: OUT[n, :NO] = act(IN[n, :K] @ W[K,NO] + bias)
// Block = 256 threads (tx = output chunk, ty = node slice), 128 nodes.
//   ACT: 0=none, 1=ssp, 2=relu ; RESID adds resid[] after relu
//   ZERO: also zero g_agg rows (node_in)
//   INSEL: 0=ext, 1=g_agg, 2=g_h2, 3=g_h3 ; OUTSEL: 0=ext, 1=g_h, 2=g_h2, 3=g_h3
// =======================================================================
template<int K, int NO, int ACT, bool RESID, bool ZERO, int INSEL, int OUTSEL>
__global__ void __launch_bounds__(256, 2) k_gemm(
    const float* __restrict__ ein, const float* __restrict__ w,
    const float* __restrict__ bias, const float* __restrict__ resid,
    float* __restrict__ eout, int N)
{
    constexpr int NC = NO / 16;          // outputs per thread (4 or 8)
    constexpr int KS = (K > 64) ? 64 : K;
    constexpr int NSTAGE = K / KS;

    __shared__ __align__(16) float sw[KS * NO];   // <= 32 KB
    __shared__ __align__(16) float sb[NO];

    int tid = threadIdx.x;
    int tx = tid & 15, ty = tid >> 4;
    if (tid < NO) sb[tid] = bias ? bias[tid] : 0.0f;

    const float* inp = (INSEL == 0) ? ein
                     : (INSEL == 1) ? (const float*)g_agg
                     : (INSEL == 2) ? (const float*)g_h2
                     :                (const float*)g_h3;
    float* outp = (OUTSEL == 0) ? eout
                : (OUTSEL == 1) ? (float*)g_h
                : (OUTSEL == 2) ? (float*)g_h2
                :                 (float*)g_h3;

    int nb = blockIdx.x * 128;
    int  nn[8];
    bool vld[8];
    #pragma unroll
    for (int r = 0; r < 8; r++){
        int n = nb + ty + 16*r;
        vld[r] = (n < N);
        nn[r]  = vld[r] ? n : 0;
    }

    ull acc[8][NC/2];
    #pragma unroll
    for (int r = 0; r < 8; r++)
        #pragma unroll
        for (int j = 0; j < NC/2; j++) acc[r][j] = 0ULL;

    #pragma unroll 1
    for (int st = 0; st < NSTAGE; st++){
        __syncthreads();
        for (int i = tid; i < KS * NO; i += 256) sw[i] = w[st*KS*NO + i];
        __syncthreads();

        #pragma unroll 1
        for (int kc = 0; kc < KS/4; kc++){
            float4 xv[8];
            #pragma unroll
            for (int r = 0; r < 8; r++)
                xv[r] = __ldg((const float4*)(inp + (size_t)nn[r]*K) + st*(KS/4) + kc);

            #pragma unroll
            for (int q = 0; q < 4; q++){
                int k = kc*4 + q;
                const ulonglong2* wr = (const ulonglong2*)(sw + k*NO + tx*NC);
                ulonglong2 wu[NC/4];
                #pragma unroll
                for (int j = 0; j < NC/4; j++) wu[j] = wr[j];

                #pragma unroll
                for (int r = 0; r < 8; r++){
                    float xq = (q == 0) ? xv[r].x : (q == 1) ? xv[r].y
                             : (q == 2) ? xv[r].z : xv[r].w;
                    ull bx = pk2(xq, xq);
                    #pragma unroll
                    for (int j = 0; j < NC/4; j++){
                        acc[r][2*j]   = ffma2(bx, wu[j].x, acc[r][2*j]);
                        acc[r][2*j+1] = ffma2(bx, wu[j].y, acc[r][2*j+1]);
                    }
                }
            }
        }
    }

    // epilogue
    const ull* sb2 = (const ull*)(sb + tx*NC);
    #pragma unroll
    for (int r = 0; r < 8; r++){
        if (!vld[r]) continue;
        int n = nn[r];
        float o[NC];
        #pragma unroll
        for (int j = 0; j < NC/2; j++){
            float2 p = up2(fadd2(acc[r][j], sb2[j]));
            if (ACT == 1){ p.x = sspf(p.x); p.y = sspf(p.y); }
            if (ACT == 2){ p.x = fmaxf(p.x, 0.f); p.y = fmaxf(p.y, 0.f); }
            o[2*j]   = p.x;
            o[2*j+1] = p.y;
        }
        if (RESID){
            const float4* rv = (const float4*)(resid + (size_t)n*NO + tx*NC);
            #pragma unroll
            for (int j = 0; j < NC/4; j++){
                float4 v = __ldg(&rv[j]);
                o[4*j]   += v.x; o[4*j+1] += v.y;
                o[4*j+2] += v.z; o[4*j+3] += v.w;
            }
        }
        float4* od = (float4*)(outp + (size_t)n*NO + tx*NC);
        #pragma unroll
        for (int j = 0; j < NC/4; j++)
            od[j] = make_float4(o[4*j], o[4*j+1], o[4*j+2], o[4*j+3]);

        if (ZERO){   // node_in: zero agg[n][tx*4 .. +4]  (NO==64, NC==4)
            float4* az = (float4*)(g_agg + (size_t)n*NF + tx*4);
            *az = make_float4(0.f, 0.f, 0.f, 0.f);
        }
    }
}

// =======================================================================
extern "C" void kernel_launch(void* const* d_in, const int* in_sizes, int n_in,
                              void* d_out, int out_size)
{
    const float* x    = (const float*)d_in[0];
    const float* pos  = (const float*)d_in[1];
    const int*   ei   = (const int*)d_in[2];
    const float* w1   = (const float*)d_in[3];
    const float* b1   = (const float*)d_in[4];
    const float* w2   = (const float*)d_in[5];
    const float* b2   = (const float*)d_in[6];
    const float* cl1  = (const float*)d_in[7];
    const float* cl2  = (const float*)d_in[8];
    const float* cl2b = (const float*)d_in[9];
    const float* ilw  = (const float*)d_in[10];
    const float* ilb  = (const float*)d_in[11];
    const float* l1w  = (const float*)d_in[12];
    const float* l1b  = (const float*)d_in[13];
    float* out = (float*)d_out;

    int N = in_sizes[0] / DIM;
    int E = in_sizes[2] / 2;

    int nb = (N + 127) / 128;
    int tb = (TBL + 1 + 31) / 32;
    long long items = (long long)E * 16;
    int eb = (int)((items + 255) / 256);

    // filter table (independent of node path)
    k_table<<<tb, 128>>>(w1, b1, w2, b2);

    // h = x @ conv_lin1_w ; zero agg
    k_gemm<DIM, NF, 0, false, true, 0, 1><<<nb, 256>>>(x, cl1, nullptr, nullptr, nullptr, N);

    // edge scatter (coalesced, 16 lanes/edge)
    k_edge<<<eb, 256>>>(ei, pos, E);

    // h2 = ssp(agg @ conv_lin2_w + b)
    k_gemm<NF, DIM, 1, false, false, 1, 2><<<nb, 256>>>(nullptr, cl2, cl2b, nullptr, nullptr, N);

    // h3 = h2 @ int_lin_w + b
    k_gemm<DIM, DIM, 0, false, false, 2, 3><<<nb, 256>>>(nullptr, ilw, ilb, nullptr, nullptr, N);

    // out = x + relu(h3 @ lin1_w + b)
    k_gemm<DIM, DIM, 2, true, false, 3, 0><<<nb, 256>>>(nullptr, l1w, l1b, x, out, N);
}